// round 4
// baseline (speedup 1.0000x reference)
#include <cuda_runtime.h>
#include <cuda_bf16.h>
#include <cstdint>

// Problem constants
#define U_DIM 20000
#define I_DIM 10000
#define K_DIM 64
#define B_DIM 4096

// Output regions (floats), reference return order.
#define OFF_SHAT   0LL
#define N_SHAT     (200000000LL)
#define OFF_UF     (OFF_SHAT + N_SHAT)           // 200,000,000
#define N_UF       (1280000LL)
#define OFF_UB     (OFF_UF + N_UF)               // 201,280,000
#define N_UB       (20000LL)
#define OFF_IF     (OFF_UB + N_UB)               // 201,300,000
#define N_IF       (640000LL)
#define OFF_IB     (OFF_IF + N_IF)               // 201,940,000
#define N_IB       (10000LL)
#define N_TOTAL    (OFF_IB + N_IB)               // 201,950,000 (divisible by 4)

#define N4_TOTAL   (N_TOTAL / 4)                 // 50,487,500 float4s
#define NBM_WORDS  ((N4_TOTAL + 31) / 32 + 2)    // bitmap words (+pad)

#define CB         32                            // compute blocks
#define CB_THREADS 256
#define CB_WARPS   (CB * (CB_THREADS / 32))      // 256 warps

#define HASH_SLOTS 16384
#define HASH_MASK  (HASH_SLOTS - 1)

// ---------------------------------------------------------------------------
// Persistent device state. Written idempotently every call (same inputs ->
// same bits/keys/flags); never cleared. Zero-initialized at module load.
// ---------------------------------------------------------------------------
__device__ unsigned      g_bitmap[NBM_WORDS];    // 1 bit per output float4
__device__ unsigned char g_usel[U_DIM];
__device__ unsigned char g_isel[I_DIM];
__device__ unsigned      g_hash[HASH_SLOTS];     // stores (u*I+i)+1, 0 = empty
__device__ unsigned      g_ready;                // monotonic across calls

__device__ __forceinline__ void set_bit(long long q) {
    atomicOr(&g_bitmap[q >> 5], 1u << ((int)q & 31));
}
// set 16 consecutive bits starting at float4 index base4 (may span 2 words)
__device__ __forceinline__ void set_bits16(long long base4) {
    long long word = base4 >> 5;
    int off = (int)base4 & 31;
    atomicOr(&g_bitmap[word], 0xFFFFu << off);
    if (off > 16) atomicOr(&g_bitmap[word + 1], 0xFFFFu >> (32 - off));
}

__device__ __forceinline__ float warp_sum(float s) {
    #pragma unroll
    for (int off = 16; off; off >>= 1)
        s += __shfl_xor_sync(0xffffffffu, s, off);
    return s;
}

__device__ __forceinline__ void wait_ready() {
    if (atomicAdd(&g_ready, 0u) >= CB) { __threadfence(); return; }
    while (atomicAdd(&g_ready, 0u) < CB) __nanosleep(64);
    __threadfence();
}

// ---------------------------------------------------------------------------
// Single fused kernel.
// blocks [0, CB): phase1 build bitmap/flags/hash -> signal; phase2 write all
//                 sparse (flagged) float4 contents.
// blocks [CB, .): wait once, then zero every float4 whose bit is clear.
// Flagged addresses are written ONLY by compute blocks; unflagged ONLY by
// zero blocks -> disjoint except duplicate-identical compute writes.
// ---------------------------------------------------------------------------
__global__ void mmf_onepass(const float* __restrict__ P,   // [U,K]
                            const float* __restrict__ Q,   // [I,K]
                            const float* __restrict__ bu,  // [U]
                            const float* __restrict__ bi,  // [I]
                            const int* __restrict__ uidx,  // [B] i32
                            const int* __restrict__ iidx,  // [B] i32
                            float* __restrict__ out,
                            long long n4, long long n_total) {
    const int tid = threadIdx.x;

    if (blockIdx.x < CB) {
        // ================= compute path =================
        // ---- phase 1: ownership marking (idempotent) ----
        int e = blockIdx.x * CB_THREADS + tid;   // 8192 threads >= B_DIM
        if (e < B_DIM) {
            int u = uidx[e];
            int i = iidx[e];
            // S_hat float4
            set_bit(((long long)u * I_DIM + i) >> 2);
            // UF row (16 float4s), IF row
            set_bits16(OFF_UF / 4 + (long long)u * (K_DIM / 4));
            set_bits16(OFF_IF / 4 + (long long)i * (K_DIM / 4));
            // UB / IB float4s
            set_bit(OFF_UB / 4 + (u >> 2));
            set_bit(OFF_IB / 4 + (i >> 2));
            g_usel[u] = 1;
            g_isel[i] = 1;
            // pair hash insert (key+1, 0 = empty)
            unsigned key = (unsigned)u * (unsigned)I_DIM + (unsigned)i + 1u;
            unsigned h = ((key * 2654435761u) >> 16) & HASH_MASK;
            for (;;) {
                unsigned prev = atomicCAS(&g_hash[h], 0u, key);
                if (prev == 0u || prev == key) break;
                h = (h + 1) & HASH_MASK;
            }
        }
        // scalar tail of output (out_size % 4), never flagged
        if (blockIdx.x == 0) {
            long long tail = n_total - 4 * n4;
            if (tid < (int)tail) out[4 * n4 + tid] = 0.f;
        }
        __syncthreads();
        if (tid == 0) {
            __threadfence();
            atomicAdd(&g_ready, 1u);
        }
        // wait for ALL compute blocks' phase 1 (hash/flags must be complete)
        if (tid == 0) wait_ready();
        __syncthreads();

        // ---- phase 2: write flagged contents (warp per entry) ----
        int wid  = (blockIdx.x * CB_THREADS + tid) >> 5;   // 0..255
        int lane = tid & 31;
        for (int ent = wid; ent < B_DIM; ent += CB_WARPS) {
            int u = uidx[ent];
            int i = iidx[ent];
            const float* pu = P + (long long)u * K_DIM;
            const float* qi = Q + (long long)i * K_DIM;
            float a0 = pu[lane], a1 = pu[lane + 32];
            float b0 = qi[lane], b1 = qi[lane + 32];

            // full factor-row copies (entire rows are flagged)
            float* uf = out + OFF_UF + (long long)u * K_DIM;
            uf[lane] = a0; uf[lane + 32] = a1;
            float* ifr = out + OFF_IF + (long long)i * K_DIM;
            ifr[lane] = b0; ifr[lane + 32] = b1;

            float s = warp_sum(fmaf(a0, b0, a1 * b1));
            float bias_u = bu[u];
            float bias_i = bi[i];

            // UB float4 containing u: lanes 0..3 write users 4*(u/4)+lane
            if (lane < 4) {
                int x = (u & ~3) + lane;
                out[OFF_UB + x] = g_usel[x] ? bu[x] : 0.f;
                int y = (i & ~3) + lane;
                out[OFF_IB + y] = g_isel[y] ? bi[y] : 0.f;
            }

            // S_hat float4 of (u,i): lanes 0..3 own columns 4c+lane
            int c = i >> 2;
            int jsel = i & 3;
            int hit = 0;
            if (lane < 4 && lane != jsel) {
                int col = (c << 2) + lane;
                unsigned key = (unsigned)u * (unsigned)I_DIM + (unsigned)col + 1u;
                unsigned h = ((key * 2654435761u) >> 16) & HASH_MASK;
                for (;;) {
                    unsigned v = g_hash[h];
                    if (v == key) { hit = 1; break; }
                    if (v == 0u) break;
                    h = (h + 1) & HASH_MASK;
                }
            }
            float myv = 0.f;
            unsigned nbmask = __ballot_sync(0xffffffffu, hit == 1);
            while (nbmask) {   // ultra-rare: another selected pair in same float4
                int j = __ffs(nbmask) - 1;
                nbmask &= nbmask - 1;
                int ncol = (c << 2) + j;
                const float* qn = Q + (long long)ncol * K_DIM;
                float sn = warp_sum(fmaf(a0, qn[lane], a1 * qn[lane + 32]));
                if (lane == j) myv = sn + bias_u + bi[ncol];
            }
            if (lane == jsel) myv = s + bias_u + bias_i;
            if (lane < 4) out[(long long)u * I_DIM + (c << 2) + lane] = myv;
        }
    } else {
        // ================= zero path (store-bandwidth bound) =================
        if (tid == 0) wait_ready();
        __syncthreads();

        long long idx = (long long)(blockIdx.x - CB) * blockDim.x + tid;
        if (idx < n4) {
            unsigned w = g_bitmap[idx >> 5];
            if (!((w >> ((int)idx & 31)) & 1u)) {
                reinterpret_cast<float4*>(out)[idx] =
                    make_float4(0.f, 0.f, 0.f, 0.f);
            }
        }
    }
}

// ---------------------------------------------------------------------------
// Launch. inputs: P [U,K] f32, Q [I,K] f32, bu [U,1] f32, bi [I] f32,
// users_idx [B] int32, items_idx [B] int32
// ---------------------------------------------------------------------------
extern "C" void kernel_launch(void* const* d_in, const int* in_sizes, int n_in,
                              void* d_out, int out_size) {
    const float* P    = (const float*)d_in[0];
    const float* Q    = (const float*)d_in[1];
    const float* bu   = (const float*)d_in[2];
    const float* bi   = (const float*)d_in[3];
    const int*   uidx = (const int*)d_in[4];
    const int*   iidx = (const int*)d_in[5];
    float* out = (float*)d_out;

    const long long n_total = (long long)out_size;   // 201,950,000
    const long long n4 = n_total / 4;

    const int threads = CB_THREADS;
    const long long blocks = CB + (n4 + threads - 1) / threads;
    mmf_onepass<<<(unsigned)blocks, threads>>>(P, Q, bu, bi, uidx, iidx,
                                               out, n4, n_total);
}

// round 5
// speedup vs baseline: 1.1169x; 1.1169x over previous
#include <cuda_runtime.h>
#include <cuda_bf16.h>
#include <cstdint>

// Problem constants
#define U_DIM 20000
#define I_DIM 10000
#define K_DIM 64
#define B_DIM 4096

// Output regions (floats), reference return order.
#define OFF_SHAT   0LL
#define N_SHAT     (200000000LL)                 // U*I
#define OFF_UF     (OFF_SHAT + N_SHAT)           // 200,000,000
#define N_UF       (1280000LL)
#define OFF_UB     (OFF_UF + N_UF)               // 201,280,000
#define N_UB       (20000LL)
#define OFF_IF     (OFF_UB + N_UB)               // 201,300,000
#define N_IF       (640000LL)
#define OFF_IB     (OFF_IF + N_IF)               // 201,940,000
#define N_IB       (10000LL)
#define N_TOTAL    (OFF_IB + N_IB)               // 201,950,000

#define N4_SHAT    (N_SHAT / 4)                  // 50,000,000 float4s
#define N4_TAIL    ((N_TOTAL - N_SHAT) / 4)      // 487,500 float4s (regions 2-5)

#define SB         32                            // scatter blocks (bid < SB)
#define THREADS    256
#define NCELL      512                           // spread done-counter cells
#define CELL_STRIDE 32                           // 32 ints = 128B apart

// ---------------------------------------------------------------------------
// Device state. All counters cycle 0 -> N -> 0 within each call (reset at the
// end of the kernel), so every launch/replay starts from zero. No allocation.
// ---------------------------------------------------------------------------
__device__ int g_done[NCELL * CELL_STRIDE];      // zero-block arrivals (spread)
__device__ int g_done_s;                         // scatter phase-b arrivals
__device__ int g_done2;                          // scatter exit handshake

__device__ __forceinline__ float warp_sum(float s) {
    #pragma unroll
    for (int off = 16; off; off >>= 1)
        s += __shfl_xor_sync(0xffffffffu, s, off);
    return s;
}

// ---------------------------------------------------------------------------
// Single fused kernel.
//  bid >= SB : zero one float4 of S_hat (pure store, no loads), then signal.
//  bid <  SB : own regions 2-5 completely (zero + fill) and compute the 4096
//              dot products into registers while the zeroing runs; wait for
//              all zero blocks; then 4096 scalar S_hat stores; reset counters.
// ---------------------------------------------------------------------------
__global__ void __launch_bounds__(THREADS)
mmf_onepass(const float* __restrict__ P,   // [U,K]
            const float* __restrict__ Q,   // [I,K]
            const float* __restrict__ bu,  // [U]
            const float* __restrict__ bi,  // [I]
            const int* __restrict__ uidx,  // [B] i32
            const int* __restrict__ iidx,  // [B] i32
            float* __restrict__ out,
            int nzero) {                   // number of zero blocks
    const int tid = threadIdx.x;
    const int bid = blockIdx.x;

    if (bid >= SB) {
        // ================= zero path: S_hat only, pure stores ================
        long long idx = (long long)(bid - SB) * THREADS + tid;
        if (idx < N4_SHAT) {
            reinterpret_cast<float4*>(out)[idx] =
                make_float4(0.f, 0.f, 0.f, 0.f);
        }
        __threadfence();        // make this thread's store visible (release)
        __syncthreads();
        if (tid == 0) {
            atomicAdd(&g_done[((bid - SB) & (NCELL - 1)) * CELL_STRIDE], 1);
        }
        return;
    }

    // ==================== scatter path (32 wave-1 blocks) ====================
    // --- phase b: zero regions 2-5 (disjoint from zero blocks) ---
    {
        float4* t4 = reinterpret_cast<float4*>(out + OFF_UF);
        for (long long q = (long long)bid * THREADS + tid; q < N4_TAIL;
             q += (long long)SB * THREADS) {
            t4[q] = make_float4(0.f, 0.f, 0.f, 0.f);
        }
    }
    __threadfence();
    __syncthreads();
    if (tid == 0) atomicAdd(&g_done_s, 1);
    if (tid == 0) {
        while (*(volatile int*)&g_done_s < SB) __nanosleep(64);
    }
    __syncthreads();
    __threadfence();   // acquire: other blocks' zeros of regions 2-5 visible

    // --- phase c: fill selected rows/biases; dots into registers ---
    const int wid  = bid * (THREADS / 32) + (tid >> 5);   // 0..255
    const int lane = tid & 31;
    int   my_u = -1, my_i = 0;
    float my_s = 0.f;

    #pragma unroll 1
    for (int k = 0; k < B_DIM / 256; ++k) {               // 16 entries per warp
        int ent = wid + k * 256;
        int u = uidx[ent];
        int i = iidx[ent];
        const float* pu = P + (long long)u * K_DIM;
        const float* qi = Q + (long long)i * K_DIM;
        float a0 = pu[lane], a1 = pu[lane + 32];
        float b0 = qi[lane], b1 = qi[lane + 32];

        float* uf = out + OFF_UF + (long long)u * K_DIM;
        uf[lane] = a0; uf[lane + 32] = a1;
        float* ifr = out + OFF_IF + (long long)i * K_DIM;
        ifr[lane] = b0; ifr[lane + 32] = b1;

        float bias_u = bu[u];
        float bias_i = bi[i];
        if (lane == 0) {
            out[OFF_UB + u] = bias_u;
            out[OFF_IB + i] = bias_i;
        }
        float s = warp_sum(fmaf(a0, b0, a1 * b1)) + bias_u + bias_i;
        if (lane == k) { my_u = u; my_i = i; my_s = s; }
    }

    // --- phase d: wait for all zero blocks ---
    __shared__ int s_part[THREADS / 32];
    __shared__ int s_tot;
    for (;;) {
        int part = 0;
        for (int c = tid; c < NCELL; c += THREADS)
            part += *(volatile int*)&g_done[c * CELL_STRIDE];
        #pragma unroll
        for (int off = 16; off; off >>= 1)
            part += __shfl_xor_sync(0xffffffffu, part, off);
        if (lane == 0) s_part[tid >> 5] = part;
        __syncthreads();
        if (tid == 0) {
            int tot = 0;
            #pragma unroll
            for (int w = 0; w < THREADS / 32; ++w) tot += s_part[w];
            s_tot = tot;
        }
        __syncthreads();
        if (s_tot == nzero) break;
        __nanosleep(1024);
    }
    __threadfence();   // acquire: zero blocks' S_hat stores visible/ordered

    // --- phase e: the sparse S_hat stores (one per held lane) ---
    if (my_u >= 0) {
        out[(long long)my_u * I_DIM + my_i] = my_s;
    }

    // --- exit handshake + counter reset (graph-replay determinism) ---
    __threadfence();
    __syncthreads();
    if (tid == 0) atomicAdd(&g_done2, 1);
    if (bid == 0) {
        if (tid == 0) {
            while (*(volatile int*)&g_done2 < SB) __nanosleep(64);
        }
        __syncthreads();
        // all scatter blocks are past every poll -> safe to reset
        for (int c = tid; c < NCELL; c += THREADS) g_done[c * CELL_STRIDE] = 0;
        if (tid == 0) { g_done_s = 0; g_done2 = 0; }
        __threadfence();
    }
}

// ---------------------------------------------------------------------------
// Launch. inputs: P [U,K] f32, Q [I,K] f32, bu [U,1] f32, bi [I] f32,
// users_idx [B] int32, items_idx [B] int32
// ---------------------------------------------------------------------------
extern "C" void kernel_launch(void* const* d_in, const int* in_sizes, int n_in,
                              void* d_out, int out_size) {
    const float* P    = (const float*)d_in[0];
    const float* Q    = (const float*)d_in[1];
    const float* bu   = (const float*)d_in[2];
    const float* bi   = (const float*)d_in[3];
    const int*   uidx = (const int*)d_in[4];
    const int*   iidx = (const int*)d_in[5];
    float* out = (float*)d_out;

    const int nzero = (int)((N4_SHAT + THREADS - 1) / THREADS); // 195,313
    const int blocks = SB + nzero;
    mmf_onepass<<<blocks, THREADS>>>(P, Q, bu, bi, uidx, iidx, out, nzero);
}

// round 6
// speedup vs baseline: 1.5027x; 1.3454x over previous
#include <cuda_runtime.h>
#include <cuda_bf16.h>
#include <cstdint>

// Problem constants
#define U_DIM 20000
#define I_DIM 10000
#define K_DIM 64
#define B_DIM 4096

// Output regions (floats), reference return order.
#define OFF_SHAT   0LL
#define N_SHAT     (200000000LL)                 // U*I
#define OFF_UF     (OFF_SHAT + N_SHAT)           // 200,000,000
#define N_UF       (1280000LL)
#define OFF_UB     (OFF_UF + N_UF)               // 201,280,000
#define N_UB       (20000LL)
#define OFF_IF     (OFF_UB + N_UB)               // 201,300,000
#define N_IF       (640000LL)
#define OFF_IB     (OFF_IF + N_IF)               // 201,940,000
#define N_IB       (10000LL)
#define N_TOTAL    (OFF_IB + N_IB)               // 201,950,000

#define N4_SHAT    (N_SHAT / 4)                  // 50,000,000 float4s
#define N4_TAIL    ((N_TOTAL - N_SHAT) / 4)      // 487,500 float4s (regions 2-5)

#define BTHREADS   256
#define NBLK       ((int)((N4_SHAT + BTHREADS - 1) / BTHREADS))  // 195,313
#define MAXENT     8                              // per-sweep-block entry cap

#define ATHREADS   256
#define ABLOCKS    128

// ---------------------------------------------------------------------------
// Device state (static, no allocation).
// g_count is reset by kernel A each call; g_ent slots <= count are rewritten
// each call with identical values; g_syncA is reset by kernel B for the next
// call. All replay-deterministic.
// ---------------------------------------------------------------------------
__device__ int   g_count[NBLK];
__device__ int   g_ent_loc[(long long)NBLK * MAXENT];  // (local_q<<2)|component
__device__ float g_ent_val[(long long)NBLK * MAXENT];
__device__ int   g_syncA;

__device__ __forceinline__ float warp_sum(float s) {
    #pragma unroll
    for (int off = 16; off; off >>= 1)
        s += __shfl_xor_sync(0xffffffffu, s, off);
    return s;
}

// ---------------------------------------------------------------------------
// Kernel A (prep): zero regions 2-5 + reset counts; barrier; fill selected
// rows/biases and build the per-sweep-block sparse entry lists.
// ---------------------------------------------------------------------------
__global__ void __launch_bounds__(ATHREADS)
mmf_prep(const float* __restrict__ P,   // [U,K]
         const float* __restrict__ Q,   // [I,K]
         const float* __restrict__ bu,  // [U]
         const float* __restrict__ bi,  // [I]
         const int* __restrict__ uidx,  // [B] i32
         const int* __restrict__ iidx,  // [B] i32
         float* __restrict__ out) {
    const int nthr = ABLOCKS * ATHREADS;
    const int t = blockIdx.x * ATHREADS + threadIdx.x;

    // ---- phase 1: zero regions 2-5 and reset per-block counts ----
    float4* t4 = reinterpret_cast<float4*>(out + OFF_UF);
    for (int q = t; q < (int)N4_TAIL; q += nthr)
        t4[q] = make_float4(0.f, 0.f, 0.f, 0.f);
    for (int c = t; c < NBLK; c += nthr)
        g_count[c] = 0;

    // ---- barrier across the 128 prep blocks (small kernel: fences cheap) ----
    __threadfence();
    __syncthreads();
    if (threadIdx.x == 0) {
        atomicAdd(&g_syncA, 1);
        while (atomicAdd(&g_syncA, 0) < ABLOCKS) __nanosleep(32);
    }
    __syncthreads();
    __threadfence();

    // ---- phase 2: warp per entry ----
    const int wid  = t >> 5;
    const int lane = t & 31;
    const int nw   = nthr >> 5;                   // 1024 warps
    for (int e = wid; e < B_DIM; e += nw) {       // 4 entries per warp
        int u = uidx[e];
        int i = iidx[e];
        const float* pu = P + (long long)u * K_DIM;
        const float* qi = Q + (long long)i * K_DIM;
        float a0 = pu[lane], a1 = pu[lane + 32];
        float b0 = qi[lane], b1 = qi[lane + 32];

        // fill masked factor rows (regions 2-5 already zeroed; same-value
        // duplicate writes across entries are benign)
        float* uf = out + OFF_UF + (long long)u * K_DIM;
        uf[lane] = a0; uf[lane + 32] = a1;
        float* ifr = out + OFF_IF + (long long)i * K_DIM;
        ifr[lane] = b0; ifr[lane + 32] = b1;

        float s = warp_sum(fmaf(a0, b0, a1 * b1));

        if (lane == 0) {
            float bias_u = bu[u];
            float bias_i = bi[i];
            out[OFF_UB + u] = bias_u;
            out[OFF_IB + i] = bias_i;

            // append S_hat sparse value to owning sweep block's list
            int flat = u * I_DIM + i;             // < 2^31
            int q4   = flat >> 2;                 // float4 index
            int blk  = q4 >> 8;                   // sweep block (256 f4/blk)
            int loc  = ((q4 & 255) << 2) | (flat & 3);
            int slot = atomicAdd(&g_count[blk], 1);
            if (slot < MAXENT) {
                g_ent_loc[(long long)blk * MAXENT + slot] = loc;
                g_ent_val[(long long)blk * MAXENT + slot] = s + bias_u + bias_i;
            }
        }
    }
}

// ---------------------------------------------------------------------------
// Kernel B (sweep): zero S_hat; the thread owning a flagged float4 writes the
// sparse value(s) instead. One uniform per-block count load is the ONLY read
// in the common path; no fences, no atomics, no spins.
// ---------------------------------------------------------------------------
__global__ void __launch_bounds__(BTHREADS)
mmf_sweep(float4* __restrict__ out4) {
    const int bid = blockIdx.x;
    const int tid = threadIdx.x;

    if (bid == 0 && tid == 0) g_syncA = 0;        // reset for next call's prep

    long long q = (long long)bid * BTHREADS + tid;
    if (q >= N4_SHAT) return;

    int cnt = g_count[bid];                       // uniform per block
    float4 v = make_float4(0.f, 0.f, 0.f, 0.f);
    if (cnt != 0) {                               // ~0.02% of blocks
        cnt = min(cnt, MAXENT);
        for (int k = 0; k < cnt; ++k) {
            int lv = g_ent_loc[(long long)bid * MAXENT + k];
            if ((lv >> 2) == tid) {
                float f = g_ent_val[(long long)bid * MAXENT + k];
                switch (lv & 3) {
                    case 0: v.x = f; break;
                    case 1: v.y = f; break;
                    case 2: v.z = f; break;
                    default: v.w = f; break;
                }
            }
        }
    }
    out4[q] = v;
}

// ---------------------------------------------------------------------------
// Launch. inputs: P [U,K] f32, Q [I,K] f32, bu [U,1] f32, bi [I] f32,
// users_idx [B] int32, items_idx [B] int32
// ---------------------------------------------------------------------------
extern "C" void kernel_launch(void* const* d_in, const int* in_sizes, int n_in,
                              void* d_out, int out_size) {
    const float* P    = (const float*)d_in[0];
    const float* Q    = (const float*)d_in[1];
    const float* bu   = (const float*)d_in[2];
    const float* bi   = (const float*)d_in[3];
    const int*   uidx = (const int*)d_in[4];
    const int*   iidx = (const int*)d_in[5];
    float* out = (float*)d_out;

    mmf_prep<<<ABLOCKS, ATHREADS>>>(P, Q, bu, bi, uidx, iidx, out);
    mmf_sweep<<<NBLK, BTHREADS>>>((float4*)out);
}

// round 7
// speedup vs baseline: 2.4299x; 1.6170x over previous
#include <cuda_runtime.h>
#include <cuda_bf16.h>
#include <cstdint>

// Problem constants
#define U_DIM 20000
#define I_DIM 10000
#define K_DIM 64
#define B_DIM 4096

// Output regions (floats), reference return order.
#define OFF_SHAT   0LL
#define N_SHAT     (200000000LL)                 // U*I
#define OFF_UF     (OFF_SHAT + N_SHAT)           // 200,000,000
#define N_UF       (1280000LL)
#define OFF_UB     (OFF_UF + N_UF)               // 201,280,000
#define N_UB       (20000LL)
#define OFF_IF     (OFF_UB + N_UB)               // 201,300,000
#define N_IF       (640000LL)
#define OFF_IB     (OFF_IF + N_IF)               // 201,940,000
#define N_IB       (10000LL)
#define N_TOTAL    (OFF_IB + N_IB)               // 201,950,000 (divisible by 4)

// ---------------------------------------------------------------------------
// Kernel 1: zero the whole output. PURE fire-and-forget float4 stores — no
// loads, no fences, no atomics (proven 7.27 TB/s; R4/R5/R6 showed any
// dependency here halves bandwidth).
// ---------------------------------------------------------------------------
__global__ void mmf_zero_kernel(float4* __restrict__ out, long long n4) {
    long long idx = (long long)blockIdx.x * blockDim.x + threadIdx.x;
    if (idx < n4) {
        out[idx] = make_float4(0.f, 0.f, 0.f, 0.f);
    }
}

__global__ void mmf_zero_tail_kernel(float* __restrict__ out,
                                     long long start, long long n) {
    long long idx = start + (long long)blockIdx.x * blockDim.x + threadIdx.x;
    if (idx < n) out[idx] = 0.f;
}

__device__ __forceinline__ float warp_sum(float s) {
    #pragma unroll
    for (int off = 16; off; off >>= 1)
        s += __shfl_xor_sync(0xffffffffu, s, off);
    return s;
}

// ---------------------------------------------------------------------------
// Kernel 2: scatter, split 3 ways for parallelism. Warp w handles entry
// e = w & 4095 with job grp = w >> 12:
//   grp 0: copy P row u -> user_factor region; write user_bias[u]
//   grp 1: copy Q row i -> item_factor region; write item_bias[i]
//   grp 2: dot(P[u], Q[i]) + bu[u] + bi[i] -> S_hat[u,i]
// 12,288 warps total; each lane uses one float2 (LDG.64) per row.
// Duplicate u/i/(u,i) across entries write identical values (benign race).
// Runs strictly after the zero kernel (same stream).
// ---------------------------------------------------------------------------
__global__ void __launch_bounds__(256)
mmf_scatter3(const float* __restrict__ P,   // [U,K]
             const float* __restrict__ Q,   // [I,K]
             const float* __restrict__ bu,  // [U]
             const float* __restrict__ bi,  // [I]
             const int* __restrict__ uidx,  // [B] i32
             const int* __restrict__ iidx,  // [B] i32
             float* __restrict__ out) {
    int g    = blockIdx.x * blockDim.x + threadIdx.x;
    int w    = g >> 5;
    int lane = g & 31;
    int e    = w & (B_DIM - 1);
    int grp  = w >> 12;                       // 0,1,2

    if (grp == 0) {
        int u = __ldg(&uidx[e]);
        const float2* pu = reinterpret_cast<const float2*>(P + (long long)u * K_DIM);
        float2 a = __ldg(&pu[lane]);
        float2* uf = reinterpret_cast<float2*>(out + OFF_UF + (long long)u * K_DIM);
        uf[lane] = a;
        if (lane == 0) out[OFF_UB + u] = __ldg(&bu[u]);
    } else if (grp == 1) {
        int i = __ldg(&iidx[e]);
        const float2* qi = reinterpret_cast<const float2*>(Q + (long long)i * K_DIM);
        float2 b = __ldg(&qi[lane]);
        float2* ifr = reinterpret_cast<float2*>(out + OFF_IF + (long long)i * K_DIM);
        ifr[lane] = b;
        if (lane == 0) out[OFF_IB + i] = __ldg(&bi[i]);
    } else {
        int u = __ldg(&uidx[e]);
        int i = __ldg(&iidx[e]);
        const float2* pu = reinterpret_cast<const float2*>(P + (long long)u * K_DIM);
        const float2* qi = reinterpret_cast<const float2*>(Q + (long long)i * K_DIM);
        float2 a = __ldg(&pu[lane]);
        float2 b = __ldg(&qi[lane]);
        float s = warp_sum(fmaf(a.x, b.x, a.y * b.y));
        if (lane == 0) {
            out[(long long)u * I_DIM + i] = s + __ldg(&bu[u]) + __ldg(&bi[i]);
        }
    }
}

// ---------------------------------------------------------------------------
// Launch. inputs: P [U,K] f32, Q [I,K] f32, bu [U,1] f32, bi [I] f32,
// users_idx [B] int32, items_idx [B] int32
// ---------------------------------------------------------------------------
extern "C" void kernel_launch(void* const* d_in, const int* in_sizes, int n_in,
                              void* d_out, int out_size) {
    const float* P    = (const float*)d_in[0];
    const float* Q    = (const float*)d_in[1];
    const float* bu   = (const float*)d_in[2];
    const float* bi   = (const float*)d_in[3];
    const int*   uidx = (const int*)d_in[4];
    const int*   iidx = (const int*)d_in[5];
    float* out = (float*)d_out;

    // 1) zero everything (808 MB pure stores — the roofline)
    const long long n_total = (long long)out_size;   // 201,950,000
    const long long n4 = n_total / 4;
    const int zthreads = 256;
    const long long zblocks = (n4 + zthreads - 1) / zthreads;
    mmf_zero_kernel<<<(unsigned)zblocks, zthreads>>>((float4*)out, n4);

    const long long tail_start = n4 * 4;
    if (tail_start < n_total) {                      // not taken (divisible)
        mmf_zero_tail_kernel<<<1, 32>>>(out, tail_start, n_total);
    }

    // 2) 3-way split scatter: 3 * 4096 warps = 1536 blocks of 256
    const int sthreads = 256;
    const int sblocks  = (3 * B_DIM * 32) / sthreads;   // 1536
    mmf_scatter3<<<sblocks, sthreads>>>(P, Q, bu, bi, uidx, iidx, out);
}